// round 3
// baseline (speedup 1.0000x reference)
#include <cuda_runtime.h>
#include <cuda_bf16.h>
#include <cstdint>

// input  [32, 64, 56, 56] fp32 -> prequantized NHWC bf16 scratch
// weight [128, 64, 3, 3]  fp32 -> prequantized [kk][n][c] bf16
// output [32, 128, 56, 56] fp32
// Implicit GEMM: M = 100352, N = 128, K = 576 (9 stages of K=64), cp.async pipelined.

#define BATCH 32
#define CIN 64
#define HW 56
#define NOUT 128
#define PIX (HW*HW)            // 3136
#define MTOT (BATCH*PIX)       // 100352
#define BM 128
#define PADK 72                // smem k-stride in bf16 (144B rows, 16B aligned, conflict-free)
#define PADE 132               // epilogue smem m-stride (floats)
#define STAGE_ELEMS (BM*PADK)  // 9216 bf16 = 18432 B per tile
#define SMEM_BYTES (4*STAGE_ELEMS*2)   // As0,Bs0,As1,Bs1 = 73728 B

__device__ __align__(16) __nv_bfloat16 g_Wq[9 * NOUT * CIN];
__device__ __align__(16) __nv_bfloat16 g_inq[(size_t)MTOT * CIN];  // NHWC bf16

__global__ void prep_weights(const float* __restrict__ w) {
    int idx = blockIdx.x * 256 + threadIdx.x;   // 73728
    if (idx < 9 * NOUT * CIN) {
        int c  = idx & 63;
        int n  = (idx >> 6) & 127;
        int kk = idx >> 13;
        g_Wq[idx] = __float2bfloat16(w[(n * CIN + c) * 9 + kk]);
    }
}

// NCHW fp32 -> NHWC bf16 quantize. 392 blocks x 256 threads, 1 pixel/thread.
__global__ void prep_input(const float* __restrict__ in) {
    int p = blockIdx.x * 256 + threadIdx.x;     // 0..100351
    int b = p / PIX;
    int r = p - b * PIX;
    const float* src = in + (size_t)(b * CIN) * PIX + r;
    __nv_bfloat16* dst = g_inq + (size_t)p * CIN;
#pragma unroll
    for (int c = 0; c < CIN; c += 8) {
        __nv_bfloat16 v[8];
#pragma unroll
        for (int j = 0; j < 8; j++) v[j] = __float2bfloat16(src[(size_t)(c + j) * PIX]);
        *reinterpret_cast<uint4*>(dst + c) = *reinterpret_cast<const uint4*>(v);
    }
}

__device__ __forceinline__ void cp16(uint32_t dst, const void* src, bool pred) {
    asm volatile("cp.async.cg.shared.global [%0], [%1], 16, %2;\n"
                 :: "r"(dst), "l"(src), "r"(pred ? 16 : 0));
}
__device__ __forceinline__ void ldmatrix_x4(uint32_t* r, uint32_t addr) {
    asm volatile("ldmatrix.sync.aligned.m8n8.x4.shared.b16 {%0,%1,%2,%3}, [%4];\n"
                 : "=r"(r[0]), "=r"(r[1]), "=r"(r[2]), "=r"(r[3]) : "r"(addr));
}
__device__ __forceinline__ void ldmatrix_x2(uint32_t* r, uint32_t addr) {
    asm volatile("ldmatrix.sync.aligned.m8n8.x2.shared.b16 {%0,%1}, [%2];\n"
                 : "=r"(r[0]), "=r"(r[1]) : "r"(addr));
}
__device__ __forceinline__ void mma_bf16(float* c, const uint32_t* a, const uint32_t* b) {
    asm volatile("mma.sync.aligned.m16n8k16.row.col.f32.bf16.bf16.f32 "
                 "{%0,%1,%2,%3}, {%4,%5,%6,%7}, {%8,%9}, {%0,%1,%2,%3};\n"
                 : "+f"(c[0]), "+f"(c[1]), "+f"(c[2]), "+f"(c[3])
                 : "r"(a[0]), "r"(a[1]), "r"(a[2]), "r"(a[3]),
                   "r"(b[0]), "r"(b[1]));
}

__global__ __launch_bounds__(256, 2)
void qconv_mma(const float* __restrict__ bias, float* __restrict__ out) {
    extern __shared__ __align__(16) unsigned char dsm[];
    __shared__ float bias_s[NOUT];
    __nv_bfloat16* tiles = reinterpret_cast<__nv_bfloat16*>(dsm);
    float* Ep = reinterpret_cast<float*>(dsm);

    const int tid  = threadIdx.x;
    const int lane = tid & 31;
    const int warp = tid >> 5;
    const int wm   = (warp & 1) * 64;
    const int wn   = (warp >> 1) * 32;

    if (tid < NOUT) bias_s[tid] = __bfloat162float(__float2bfloat16(bias[tid]));

    // loader mapping: each thread fills half of one tile row (4 x 16B cp.async per tile)
    const int lrow  = tid >> 1;
    const int lhalf = tid & 1;
    const int lm  = blockIdx.x * BM + lrow;
    const int lb  = lm / PIX;
    const int lr  = lm - lb * PIX;
    const int loh = lr / HW;
    const int low = lr - loh * HW;

    const uint32_t smem_u32 = (uint32_t)__cvta_generic_to_shared(tiles);

    float acc[4][4][4];
#pragma unroll
    for (int mi = 0; mi < 4; mi++)
#pragma unroll
        for (int ni = 0; ni < 4; ni++)
#pragma unroll
            for (int j = 0; j < 4; j++) acc[mi][ni][j] = 0.f;

    auto issue_stage = [&](int kk, int s) {
        const int kh = kk / 3, kw = kk - kh * 3;
        const int ih = loh + kh - 1, iw = low + kw - 1;
        const bool valid = ((unsigned)ih < HW) && ((unsigned)iw < HW);
        // valid => halo pixel linear index = lm + (kh-1)*HW + (kw-1) (same batch)
        const __nv_bfloat16* srcA =
            g_inq + (size_t)(lm + (kh - 1) * HW + (kw - 1)) * CIN + lhalf * 32;
        uint32_t dstA = smem_u32 + (uint32_t)(s * 2 * STAGE_ELEMS + lrow * PADK + lhalf * 32) * 2;
#pragma unroll
        for (int j = 0; j < 4; j++) cp16(dstA + j * 16, srcA + j * 8, valid);

        const __nv_bfloat16* srcB = g_Wq + kk * (NOUT * CIN) + lrow * CIN + lhalf * 32;
        uint32_t dstB = smem_u32 + (uint32_t)((s * 2 + 1) * STAGE_ELEMS + lrow * PADK + lhalf * 32) * 2;
#pragma unroll
        for (int j = 0; j < 4; j++) cp16(dstB + j * 16, srcB + j * 8, true);
        asm volatile("cp.async.commit_group;\n");
    };

    issue_stage(0, 0);

#pragma unroll 1
    for (int kk = 0; kk < 9; kk++) {
        const int s = kk & 1;
        if (kk + 1 < 9) {
            issue_stage(kk + 1, s ^ 1);
            asm volatile("cp.async.wait_group 1;\n");
        } else {
            asm volatile("cp.async.wait_group 0;\n");
        }
        __syncthreads();

        const uint32_t asmem = smem_u32 + (uint32_t)(s * 2 * STAGE_ELEMS) * 2;
        const uint32_t bsmem = asmem + STAGE_ELEMS * 2;

#pragma unroll
        for (int ks = 0; ks < 4; ks++) {
            uint32_t af[4][4];
#pragma unroll
            for (int mi = 0; mi < 4; mi++) {
                uint32_t addr = asmem +
                    (uint32_t)(((wm + mi * 16 + (lane & 15)) * PADK) + ks * 16 + (lane >> 4) * 8) * 2;
                ldmatrix_x4(af[mi], addr);
            }
            uint32_t bfr[4][2];
#pragma unroll
            for (int ni = 0; ni < 4; ni++) {
                uint32_t addr = bsmem +
                    (uint32_t)(((wn + ni * 8 + (lane & 7)) * PADK) + ks * 16 + ((lane >> 3) & 1) * 8) * 2;
                ldmatrix_x2(bfr[ni], addr);
            }
#pragma unroll
            for (int mi = 0; mi < 4; mi++)
#pragma unroll
                for (int ni = 0; ni < 4; ni++)
                    mma_bf16(acc[mi][ni], af[mi], bfr[ni]);
        }
        __syncthreads();
    }

    // ---- Epilogue: two passes of 64 channels through smem transpose ----
    const int m_l = tid & 127;
    const int em  = blockIdx.x * BM + m_l;
    const int eb  = em / PIX;
    const int er  = em - eb * PIX;
    const long long obase = (long long)eb * (NOUT * PIX) + er;

#pragma unroll 1
    for (int p = 0; p < 2; p++) {
        if ((wn >> 6) == p) {
#pragma unroll
            for (int mi = 0; mi < 4; mi++)
#pragma unroll
                for (int ni = 0; ni < 4; ni++) {
                    int ncol = (wn & 63) + ni * 8 + 2 * (lane & 3);
                    int mrow = wm + mi * 16 + (lane >> 2);
                    Ep[(ncol + 0) * PADE + mrow]     = acc[mi][ni][0];
                    Ep[(ncol + 1) * PADE + mrow]     = acc[mi][ni][1];
                    Ep[(ncol + 0) * PADE + mrow + 8] = acc[mi][ni][2];
                    Ep[(ncol + 1) * PADE + mrow + 8] = acc[mi][ni][3];
                }
        }
        __syncthreads();
#pragma unroll
        for (int i = 0; i < 32; i++) {
            int n_l = (tid >> 7) + 2 * i;     // 0..63
            float v = Ep[n_l * PADE + m_l] + bias_s[p * 64 + n_l];
            out[obase + (long long)(p * 64 + n_l) * PIX] = v;
        }
        __syncthreads();
    }
}

extern "C" void kernel_launch(void* const* d_in, const int* in_sizes, int n_in,
                              void* d_out, int out_size) {
    const float* inp    = (const float*)d_in[0];
    const float* weight = (const float*)d_in[1];
    const float* bias   = (const float*)d_in[2];
    float* out = (float*)d_out;
    (void)in_sizes; (void)n_in; (void)out_size;

    cudaFuncSetAttribute(qconv_mma, cudaFuncAttributeMaxDynamicSharedMemorySize, SMEM_BYTES);

    prep_weights<<<(9 * NOUT * CIN + 255) / 256, 256>>>(weight);
    prep_input<<<MTOT / 256, 256>>>(inp);
    qconv_mma<<<MTOT / BM, 256, SMEM_BYTES>>>(bias, out);
}

// round 6
// speedup vs baseline: 1.0231x; 1.0231x over previous
#include <cuda_runtime.h>
#include <cuda_bf16.h>
#include <cstdint>

// input  [32, 64, 56, 56] fp32 -> prequantized NHWC bf16 (g_inq)
// weight [128, 64, 3, 3]  fp32 -> prequantized [kk][n][c] bf16 (g_Wq)
// output [32, 128, 56, 56] fp32
// Implicit GEMM (mma.sync bf16): M=100352, N=128, K=576 (9 stages x 64),
// cp.async double-buffered, one barrier per stage.

#define HW 56
#define CIN 64
#define NOUT 128
#define PIX (HW*HW)            // 3136
#define MTOT (32*PIX)          // 100352
#define BM 128
#define PADK 72                // smem k-stride in bf16 (144B rows, conflict-free)
#define PADE 132               // epilogue smem m-stride (floats)
#define STAGE_ELEMS (BM*PADK)  // 9216 bf16 per tile (A or B)
#define SMEM_BYTES (4*STAGE_ELEMS*2)   // A0,B0,A1,B1 = 73728 B

__device__ __align__(16) __nv_bfloat16 g_Wq[9 * NOUT * CIN];
__device__ __align__(16) __nv_bfloat16 g_inq[(size_t)MTOT * CIN];

__global__ void prep_weights(const float* __restrict__ w) {
    int idx = blockIdx.x * 256 + threadIdx.x;   // 73728
    if (idx < 9 * NOUT * CIN) {
        int c  = idx & 63;
        int n  = (idx >> 6) & 127;
        int kk = idx >> 13;
        g_Wq[idx] = __float2bfloat16(w[(n * CIN + c) * 9 + kk]);
    }
}

// NCHW fp32 -> NHWC bf16 quantize
__global__ void prep_input(const float* __restrict__ in) {
    int p = blockIdx.x * 256 + threadIdx.x;     // 0..100351
    int b = p / PIX;
    int r = p - b * PIX;
    const float* src = in + (size_t)(b * CIN) * PIX + r;
    __nv_bfloat16* dst = g_inq + (size_t)p * CIN;
#pragma unroll
    for (int c = 0; c < CIN; c += 8) {
        __nv_bfloat16 v[8];
#pragma unroll
        for (int j = 0; j < 8; j++) v[j] = __float2bfloat16(src[(size_t)(c + j) * PIX]);
        *reinterpret_cast<uint4*>(dst + c) = *reinterpret_cast<const uint4*>(v);
    }
}

__device__ __forceinline__ void cp16(uint32_t dst, const void* src, bool v) {
    asm volatile("cp.async.cg.shared.global [%0], [%1], 16, %2;\n"
                 :: "r"(dst), "l"(src), "r"(v ? 16 : 0));
}
__device__ __forceinline__ void ldmatrix_x4(uint32_t* r, uint32_t addr) {
    asm volatile("ldmatrix.sync.aligned.m8n8.x4.shared.b16 {%0,%1,%2,%3}, [%4];\n"
                 : "=r"(r[0]), "=r"(r[1]), "=r"(r[2]), "=r"(r[3]) : "r"(addr));
}
__device__ __forceinline__ void mma_bf16(float* c, const uint32_t* a, const uint32_t* b) {
    asm volatile("mma.sync.aligned.m16n8k16.row.col.f32.bf16.bf16.f32 "
                 "{%0,%1,%2,%3}, {%4,%5,%6,%7}, {%8,%9}, {%0,%1,%2,%3};\n"
                 : "+f"(c[0]), "+f"(c[1]), "+f"(c[2]), "+f"(c[3])
                 : "r"(a[0]), "r"(a[1]), "r"(a[2]), "r"(a[3]),
                   "r"(b[0]), "r"(b[1]));
}
__device__ __forceinline__ void stg_cs(float* p, float v) {
    asm volatile("st.global.cs.f32 [%0], %1;" :: "l"(p), "f"(v) : "memory");
}

__global__ __launch_bounds__(256, 2)
void qconv_mma(const float* __restrict__ bias, float* __restrict__ out) {
    extern __shared__ __align__(16) unsigned char dsm[];
    __shared__ float bias_s[NOUT];
    __nv_bfloat16* tiles = reinterpret_cast<__nv_bfloat16*>(dsm);
    float* Ep = reinterpret_cast<float*>(dsm);

    const int tid  = threadIdx.x;
    const int lane = tid & 31;
    const int warp = tid >> 5;
    const int wm   = (warp & 1) * 64;
    const int wn   = (warp >> 1) * 32;

    if (tid < NOUT) bias_s[tid] = __bfloat162float(__float2bfloat16(bias[tid]));

    // loader mapping: thread owns (row tid>>1, half tid&1): 4 x 16B per tile
    const int lrow  = tid >> 1;
    const int lhalf = tid & 1;
    const int lm  = blockIdx.x * BM + lrow;
    const int lb  = lm / PIX;
    const int lr  = lm - lb * PIX;
    const int loh = lr / HW;
    const int low = lr - loh * HW;

    const uint32_t smem_u32 = (uint32_t)__cvta_generic_to_shared(tiles);

    float acc[4][4][4];
#pragma unroll
    for (int mi = 0; mi < 4; mi++)
#pragma unroll
        for (int ni = 0; ni < 4; ni++)
#pragma unroll
            for (int j = 0; j < 4; j++) acc[mi][ni][j] = 0.f;

    auto issue = [&](int kk, int s) {
        const int kh = kk / 3, kw = kk - kh * 3;
        const int ih = loh + kh - 1, iw = low + kw - 1;
        const bool valid = ((unsigned)ih < HW) && ((unsigned)iw < HW);
        const __nv_bfloat16* srcA =
            g_inq + (size_t)(lm + (kh - 1) * HW + (kw - 1)) * CIN + lhalf * 32;
        uint32_t dstA = smem_u32 + (uint32_t)(s * 2 * STAGE_ELEMS + lrow * PADK + lhalf * 32) * 2;
#pragma unroll
        for (int j = 0; j < 4; j++) cp16(dstA + j * 16, srcA + j * 8, valid);

        const __nv_bfloat16* srcB = g_Wq + kk * (NOUT * CIN) + lrow * CIN + lhalf * 32;
        uint32_t dstB = smem_u32 + (uint32_t)((s * 2 + 1) * STAGE_ELEMS + lrow * PADK + lhalf * 32) * 2;
#pragma unroll
        for (int j = 0; j < 4; j++) cp16(dstB + j * 16, srcB + j * 8, true);
        asm volatile("cp.async.commit_group;\n" ::: "memory");
    };

    issue(0, 0);

#pragma unroll 1
    for (int kk = 0; kk < 9; kk++) {
        const int s = kk & 1;
        asm volatile("cp.async.wait_group 0;\n" ::: "memory");
        __syncthreads();                 // data s visible; buffer s^1 free
        if (kk < 8) issue(kk + 1, s ^ 1);

        const uint32_t asmem = smem_u32 + (uint32_t)(s * 2 * STAGE_ELEMS) * 2;
        const uint32_t bsmem = asmem + STAGE_ELEMS * 2;

#pragma unroll
        for (int ks = 0; ks < 4; ks++) {
            uint32_t af[4][4];
#pragma unroll
            for (int mi = 0; mi < 4; mi++) {
                uint32_t addr = asmem +
                    (uint32_t)(((wm + mi * 16 + (lane & 15)) * PADK) + ks * 16 + (lane >> 4) * 8) * 2;
                ldmatrix_x4(af[mi], addr);
            }
            uint32_t bfr[4][2];
#pragma unroll
            for (int np = 0; np < 2; np++) {     // x4 loads two n8 tiles at once
                uint32_t row = wn + np * 16 + (lane >> 4) * 8 + (lane & 7);
                uint32_t addr = bsmem +
                    (uint32_t)((row * PADK) + ks * 16 + ((lane >> 3) & 1) * 8) * 2;
                uint32_t r4[4];
                ldmatrix_x4(r4, addr);
                bfr[np * 2][0] = r4[0]; bfr[np * 2][1] = r4[1];
                bfr[np * 2 + 1][0] = r4[2]; bfr[np * 2 + 1][1] = r4[3];
            }
#pragma unroll
            for (int mi = 0; mi < 4; mi++)
#pragma unroll
                for (int ni = 0; ni < 4; ni++)
                    mma_bf16(acc[mi][ni], af[mi], bfr[ni]);
        }
        __syncthreads();                 // all reads of buffer s done before reuse
    }

    // ---- Epilogue: two passes of 64 channels through smem transpose ----
    const int m_l = tid & 127;
    const int em  = blockIdx.x * BM + m_l;
    const int eb  = em / PIX;
    const int er  = em - eb * PIX;
    const long long obase = (long long)eb * (NOUT * PIX) + er;

#pragma unroll 1
    for (int p = 0; p < 2; p++) {
        if ((wn >> 6) == p) {
#pragma unroll
            for (int mi = 0; mi < 4; mi++)
#pragma unroll
                for (int ni = 0; ni < 4; ni++) {
                    int ncol = (wn & 63) + ni * 8 + 2 * (lane & 3);
                    int mrow = wm + mi * 16 + (lane >> 2);
                    Ep[(ncol + 0) * PADE + mrow]     = acc[mi][ni][0];
                    Ep[(ncol + 1) * PADE + mrow]     = acc[mi][ni][1];
                    Ep[(ncol + 0) * PADE + mrow + 8] = acc[mi][ni][2];
                    Ep[(ncol + 1) * PADE + mrow + 8] = acc[mi][ni][3];
                }
        }
        __syncthreads();
#pragma unroll
        for (int i = 0; i < 32; i++) {
            int n_l = (tid >> 7) + 2 * i;     // 0..63
            float v = Ep[n_l * PADE + m_l] + bias_s[p * 64 + n_l];
            stg_cs(out + obase + (long long)(p * 64 + n_l) * PIX, v);
        }
        __syncthreads();
    }
}

extern "C" void kernel_launch(void* const* d_in, const int* in_sizes, int n_in,
                              void* d_out, int out_size) {
    const float* inp    = (const float*)d_in[0];
    const float* weight = (const float*)d_in[1];
    const float* bias   = (const float*)d_in[2];
    float* out = (float*)d_out;
    (void)in_sizes; (void)n_in; (void)out_size;

    cudaFuncSetAttribute(qconv_mma, cudaFuncAttributeMaxDynamicSharedMemorySize, SMEM_BYTES);

    prep_weights<<<(9 * NOUT * CIN + 255) / 256, 256>>>(weight);
    prep_input<<<MTOT / 256, 256>>>(inp);
    qconv_mma<<<MTOT / BM, 256, SMEM_BYTES>>>(bias, out);
}

// round 7
// speedup vs baseline: 1.1583x; 1.1321x over previous
#include <cuda_runtime.h>
#include <cuda_bf16.h>
#include <cstdint>

// input  [32, 64, 56, 56] fp32 -> zero-padded halo NHWC bf16 g_inq[32][58][58][64]
// weight [128, 64, 3, 3]  fp32 -> prequantized [kk][n][c] bf16 g_Wq
// output [32, 128, 56, 56] fp32
// Implicit GEMM (mma.sync bf16). BM=112 = two output rows of one image.
// A = single 232-row halo window loaded once; B triple-buffered cp.async.

#define HW 56
#define CIN 64
#define NOUT 128
#define PIX (HW*HW)            // 3136
#define MTOT (32*PIX)          // 100352
#define BM 112
#define NCTA (MTOT/BM)         // 896
#define HLW 58                 // halo width
#define HPIX (HLW*HLW)         // 3364 halo pixels per image
#define AROWS 232              // 4 halo rows x 58
#define ROWB 144               // bytes per smem row (72 bf16, conflict-free)
#define A_BYTES (AROWS*ROWB)   // 33408
#define B_BYTES (NOUT*ROWB)    // 18432
#define SMEM_ALLOC (A_BYTES + 3*B_BYTES)   // 88704
#define PADE 117               // epilogue float stride (odd -> conflict-free)

__device__ __align__(16) __nv_bfloat16 g_Wq[9 * NOUT * CIN];
__device__ __align__(16) __nv_bfloat16 g_inq[(size_t)32 * HPIX * CIN];

// Fused prep: blocks [0,288) quantize weights, blocks [288,709) build halo input.
__global__ void prep_all(const float* __restrict__ w, const float* __restrict__ in) {
    if (blockIdx.x < 288) {
        int idx = blockIdx.x * 256 + threadIdx.x;   // 73728
        if (idx < 9 * NOUT * CIN) {
            int c  = idx & 63;
            int n  = (idx >> 6) & 127;
            int kk = idx >> 13;
            g_Wq[idx] = __float2bfloat16(w[(n * CIN + c) * 9 + kk]);
        }
        return;
    }
    int pid = (blockIdx.x - 288) * 256 + threadIdx.x;   // halo pixel id
    if (pid >= 32 * HPIX) return;
    int b   = pid / HPIX;
    int rem = pid - b * HPIX;
    int hh  = rem / HLW;
    int ww  = rem - hh * HLW;
    __nv_bfloat16* dst = g_inq + (size_t)pid * CIN;
    bool inside = (hh >= 1) && (hh <= HW) && (ww >= 1) && (ww <= HW);
    if (inside) {
        const float* src = in + ((size_t)b * CIN) * PIX + (hh - 1) * HW + (ww - 1);
#pragma unroll
        for (int c = 0; c < CIN; c += 8) {
            __nv_bfloat16 v[8];
#pragma unroll
            for (int j = 0; j < 8; j++) v[j] = __float2bfloat16(src[(size_t)(c + j) * PIX]);
            *reinterpret_cast<uint4*>(dst + c) = *reinterpret_cast<const uint4*>(v);
        }
    } else {
        uint4 z = make_uint4(0, 0, 0, 0);
#pragma unroll
        for (int c = 0; c < CIN; c += 8) *reinterpret_cast<uint4*>(dst + c) = z;
    }
}

__device__ __forceinline__ void cp16(uint32_t dst, const void* src) {
    asm volatile("cp.async.cg.shared.global [%0], [%1], 16;\n" :: "r"(dst), "l"(src));
}
__device__ __forceinline__ void ldmatrix_x4(uint32_t* r, uint32_t addr) {
    asm volatile("ldmatrix.sync.aligned.m8n8.x4.shared.b16 {%0,%1,%2,%3}, [%4];\n"
                 : "=r"(r[0]), "=r"(r[1]), "=r"(r[2]), "=r"(r[3]) : "r"(addr));
}
__device__ __forceinline__ void mma_bf16(float* c, const uint32_t* a, const uint32_t* b) {
    asm volatile("mma.sync.aligned.m16n8k16.row.col.f32.bf16.bf16.f32 "
                 "{%0,%1,%2,%3}, {%4,%5,%6,%7}, {%8,%9}, {%0,%1,%2,%3};\n"
                 : "+f"(c[0]), "+f"(c[1]), "+f"(c[2]), "+f"(c[3])
                 : "r"(a[0]), "r"(a[1]), "r"(a[2]), "r"(a[3]),
                   "r"(b[0]), "r"(b[1]));
}
__device__ __forceinline__ void stg_cs(float* p, float v) {
    asm volatile("st.global.cs.f32 [%0], %1;" :: "l"(p), "f"(v) : "memory");
}

__global__ __launch_bounds__(256, 2)
void qconv_mma(const float* __restrict__ bias, float* __restrict__ out) {
    extern __shared__ __align__(16) unsigned char dsm[];
    __shared__ float bias_s[NOUT];
    float* Ep = reinterpret_cast<float*>(dsm);

    const int tid  = threadIdx.x;
    const int lane = tid & 31;
    const int warp = tid >> 5;
    const int wm   = (warp & 1) * 64;          // 0 or 64
    const int wn   = (warp >> 1) * 32;         // 0,32,64,96
    const int MI   = (warp & 1) ? 3 : 4;       // m tiles: 0..111

    if (tid < NOUT) bias_s[tid] = __bfloat162float(__float2bfloat16(bias[tid]));

    // CTA geometry: 28 CTAs per image, 2 output rows each
    const int b  = blockIdx.x / 28;
    const int h0 = (blockIdx.x - b * 28) * 2;
    const size_t P0 = ((size_t)b * HLW + h0) * HLW;   // first halo pixel of A window

    const uint32_t smem_u32 = (uint32_t)__cvta_generic_to_shared(dsm);
    const uint32_t Ab = smem_u32;                      // A window
    // B buffers: smem_u32 + A_BYTES + s*B_BYTES

    // per-lane A row bases: m -> halo row offset within window
    int rb[4];
#pragma unroll
    for (int mi = 0; mi < 4; mi++) {
        int m = wm + mi * 16 + (lane & 15);
        rb[mi] = (m / HW) * HLW + (m % HW);            // 0..113
    }

    float acc[4][4][4];
#pragma unroll
    for (int mi = 0; mi < 4; mi++)
#pragma unroll
        for (int ni = 0; ni < 4; ni++)
#pragma unroll
            for (int j = 0; j < 4; j++) acc[mi][ni][j] = 0.f;

    // ---- prologue: A window (232 rows x 128B), one commit group ----
#pragma unroll
    for (int it = 0; it < 8; it++) {
        int idx = tid + it * 256;                      // 0..2047, need <1856
        if (idx < AROWS * 8) {
            int row = idx >> 3, q = idx & 7;
            cp16(Ab + row * ROWB + q * 16, g_inq + (P0 + row) * CIN + q * 8);
        }
    }
    asm volatile("cp.async.commit_group;\n" ::: "memory");

    // B loader: thread covers (row tid>>1, half tid&1): 4 x 16B
    const int brow = tid >> 1, bhalf = tid & 1;
    auto issueB = [&](int kk, int s) {
        const __nv_bfloat16* srcB = g_Wq + kk * (NOUT * CIN) + brow * CIN + bhalf * 32;
        uint32_t dstB = smem_u32 + A_BYTES + (uint32_t)s * B_BYTES
                        + (uint32_t)brow * ROWB + (uint32_t)bhalf * 64;
#pragma unroll
        for (int j = 0; j < 4; j++) cp16(dstB + j * 16, srcB + j * 8);
        asm volatile("cp.async.commit_group;\n" ::: "memory");
    };

    issueB(0, 0);
    issueB(1, 1);

#pragma unroll 1
    for (int kk = 0; kk < 9; kk++) {
        if (kk < 8) asm volatile("cp.async.wait_group 1;\n" ::: "memory");
        else        asm volatile("cp.async.wait_group 0;\n" ::: "memory");
        __syncthreads();        // stage kk data visible; buffer (kk+2)%3 reads done
        if (kk < 7) issueB(kk + 2, (kk + 2) % 3);

        const int kh = kk / 3, kw = kk - kh * 3;
        const uint32_t aoff = (uint32_t)(kh * HLW + kw) * ROWB + (uint32_t)(lane >> 4) * 16;
        const uint32_t bbase = smem_u32 + A_BYTES + (uint32_t)(kk % 3) * B_BYTES;

#pragma unroll
        for (int ks = 0; ks < 4; ks++) {
            uint32_t af[4][4];
#pragma unroll
            for (int mi = 0; mi < 4; mi++) {
                if (mi < MI) {
                    uint32_t addr = Ab + (uint32_t)rb[mi] * ROWB + aoff + ks * 32;
                    ldmatrix_x4(af[mi], addr);
                }
            }
            uint32_t bfr[4][2];
#pragma unroll
            for (int np = 0; np < 2; np++) {
                uint32_t row = wn + np * 16 + (lane >> 4) * 8 + (lane & 7);
                uint32_t addr = bbase + row * ROWB + ks * 32 + ((lane >> 3) & 1) * 16;
                uint32_t r4[4];
                ldmatrix_x4(r4, addr);
                bfr[np * 2][0] = r4[0]; bfr[np * 2][1] = r4[1];
                bfr[np * 2 + 1][0] = r4[2]; bfr[np * 2 + 1][1] = r4[3];
            }
#pragma unroll
            for (int mi = 0; mi < 4; mi++) {
                if (mi < MI) {
#pragma unroll
                    for (int ni = 0; ni < 4; ni++)
                        mma_bf16(acc[mi][ni], af[mi], bfr[ni]);
                }
            }
        }
        __syncthreads();        // all reads of stage kk buffers done
    }

    // ---- epilogue: smem transpose, two 64-channel passes ----
    const int m_l  = tid % BM;                // 0..111
    const int half = tid / BM;                // 0,1 (tid>=224 idle on stores)
    float* ob = out + (size_t)b * (NOUT * PIX) + h0 * HW;

#pragma unroll 1
    for (int p = 0; p < 2; p++) {
        if ((wn >> 6) == p) {
#pragma unroll
            for (int mi = 0; mi < 4; mi++) {
                if (mi < MI) {
#pragma unroll
                    for (int ni = 0; ni < 4; ni++) {
                        int ncol = (wn & 63) + ni * 8 + 2 * (lane & 3);
                        int mrow = wm + mi * 16 + (lane >> 2);
                        Ep[(ncol + 0) * PADE + mrow]     = acc[mi][ni][0];
                        Ep[(ncol + 1) * PADE + mrow]     = acc[mi][ni][1];
                        Ep[(ncol + 0) * PADE + mrow + 8] = acc[mi][ni][2];
                        Ep[(ncol + 1) * PADE + mrow + 8] = acc[mi][ni][3];
                    }
                }
            }
        }
        __syncthreads();
        if (tid < 2 * BM) {
#pragma unroll
            for (int i = 0; i < 32; i++) {
                int n_l = half + 2 * i;       // 0..63
                float v = Ep[n_l * PADE + m_l] + bias_s[p * 64 + n_l];
                stg_cs(ob + (size_t)(p * 64 + n_l) * PIX + m_l, v);
            }
        }
        __syncthreads();
    }
}

extern "C" void kernel_launch(void* const* d_in, const int* in_sizes, int n_in,
                              void* d_out, int out_size) {
    const float* inp    = (const float*)d_in[0];
    const float* weight = (const float*)d_in[1];
    const float* bias   = (const float*)d_in[2];
    float* out = (float*)d_out;
    (void)in_sizes; (void)n_in; (void)out_size;

    cudaFuncSetAttribute(qconv_mma, cudaFuncAttributeMaxDynamicSharedMemorySize, SMEM_ALLOC);

    prep_all<<<288 + (32 * HPIX + 255) / 256, 256>>>(weight, inp);
    qconv_mma<<<NCTA, 256, SMEM_ALLOC>>>(bias, out);
}

// round 8
// speedup vs baseline: 1.3518x; 1.1671x over previous
#include <cuda_runtime.h>
#include <cuda_bf16.h>
#include <cstdint>

// input  [32, 64, 56, 56] fp32 -> zero-padded halo NHWC bf16 g_inq[32][58][58][64]
// weight [128, 64, 3, 3]  fp32 -> prequantized [kk][n][c] bf16 g_Wq
// output [32, 128, 56, 56] fp32
// Implicit GEMM (mma.sync bf16). BM=128 pixels (image padded to 25 tiles).
// A = 348-halo-row window loaded once (SW128 swizzle, 128B rows);
// B triple-buffered cp.async (SW128). One barrier per K-stage.

#define HW 56
#define CIN 64
#define NOUT 128
#define PIX (HW*HW)            // 3136
#define HLW 58
#define HPIX (HLW*HLW)         // 3364
#define BM 128
#define TPI 25                 // tiles per image (25*128 = 3200 >= 3136)
#define NCTA (32*TPI)          // 800
#define AROWS 348              // 6 halo rows x 58
#define A_BYTES (AROWS*128)    // 44544
#define B_BYTES (NOUT*128)     // 16384
#define SMEM_ALLOC (A_BYTES + 3*B_BYTES)   // 93696
#define PADE 132               // epilogue float stride

__device__ __align__(16) __nv_bfloat16 g_Wq[9 * NOUT * CIN];
__device__ __align__(16) __nv_bfloat16 g_inq[((size_t)32 * HPIX + 1024) * CIN]; // +slack

// Fused prep: blocks [0,288) quantize weights, rest build halo input.
__global__ void prep_all(const float* __restrict__ w, const float* __restrict__ in) {
    if (blockIdx.x < 288) {
        int idx = blockIdx.x * 256 + threadIdx.x;   // 73728
        if (idx < 9 * NOUT * CIN) {
            int c  = idx & 63;
            int n  = (idx >> 6) & 127;
            int kk = idx >> 13;
            g_Wq[idx] = __float2bfloat16(w[(n * CIN + c) * 9 + kk]);
        }
        return;
    }
    int pid = (blockIdx.x - 288) * 256 + threadIdx.x;
    if (pid >= 32 * HPIX) return;
    int b   = pid / HPIX;
    int rem = pid - b * HPIX;
    int hh  = rem / HLW;
    int ww  = rem - hh * HLW;
    __nv_bfloat16* dst = g_inq + (size_t)pid * CIN;
    bool inside = (hh >= 1) && (hh <= HW) && (ww >= 1) && (ww <= HW);
    if (inside) {
        const float* src = in + ((size_t)b * CIN) * PIX + (hh - 1) * HW + (ww - 1);
#pragma unroll
        for (int c = 0; c < CIN; c += 8) {
            __nv_bfloat16 v[8];
#pragma unroll
            for (int j = 0; j < 8; j++) v[j] = __float2bfloat16(src[(size_t)(c + j) * PIX]);
            *reinterpret_cast<uint4*>(dst + c) = *reinterpret_cast<const uint4*>(v);
        }
    } else {
        uint4 z = make_uint4(0, 0, 0, 0);
#pragma unroll
        for (int c = 0; c < CIN; c += 8) *reinterpret_cast<uint4*>(dst + c) = z;
    }
}

__device__ __forceinline__ void cp16(uint32_t dst, const void* src) {
    asm volatile("cp.async.cg.shared.global [%0], [%1], 16;\n" :: "r"(dst), "l"(src));
}
__device__ __forceinline__ void ldmatrix_x4(uint32_t* r, uint32_t addr) {
    asm volatile("ldmatrix.sync.aligned.m8n8.x4.shared.b16 {%0,%1,%2,%3}, [%4];\n"
                 : "=r"(r[0]), "=r"(r[1]), "=r"(r[2]), "=r"(r[3]) : "r"(addr));
}
__device__ __forceinline__ void mma_bf16(float* c, const uint32_t* a, const uint32_t* b) {
    asm volatile("mma.sync.aligned.m16n8k16.row.col.f32.bf16.bf16.f32 "
                 "{%0,%1,%2,%3}, {%4,%5,%6,%7}, {%8,%9}, {%0,%1,%2,%3};\n"
                 : "+f"(c[0]), "+f"(c[1]), "+f"(c[2]), "+f"(c[3])
                 : "r"(a[0]), "r"(a[1]), "r"(a[2]), "r"(a[3]),
                   "r"(b[0]), "r"(b[1]));
}
__device__ __forceinline__ void stg_cs(float* p, float v) {
    asm volatile("st.global.cs.f32 [%0], %1;" :: "l"(p), "f"(v) : "memory");
}

__global__ __launch_bounds__(256, 2)
void qconv_mma(const float* __restrict__ bias, float* __restrict__ out) {
    extern __shared__ __align__(16) unsigned char dsm[];
    __shared__ float bias_s[NOUT];
    float* Ep = reinterpret_cast<float*>(dsm);

    const int tid  = threadIdx.x;
    const int lane = tid & 31;
    const int warp = tid >> 5;
    const int wm   = (warp & 1) * 64;          // 0 or 64
    const int wn   = (warp >> 1) * 32;         // 0,32,64,96

    if (tid < NOUT) bias_s[tid] = __bfloat162float(__float2bfloat16(bias[tid]));

    // CTA geometry: image b, tile t (128 pixels, may include dummies past 3136)
    const int b  = blockIdx.x / TPI;
    const int t  = blockIdx.x - b * TPI;
    const int q0 = t * BM;                       // first pixel of tile
    const int oh0 = q0 / HW;                     // first output row touched
    const size_t S0 = ((size_t)b * HLW + oh0) * HLW;  // halo window base pixel

    const uint32_t smem_u32 = (uint32_t)__cvta_generic_to_shared(dsm);
    const uint32_t Ab = smem_u32;

    // per-lane A row bases within the halo window (row units of 128B)
    int rb[4];
#pragma unroll
    for (int mi = 0; mi < 4; mi++) {
        int q = q0 + wm + mi * 16 + (lane & 15);
        rb[mi] = (q / HW - oh0) * HLW + (q % HW);    // 0..~289
    }

    float acc[4][4][4];
#pragma unroll
    for (int mi = 0; mi < 4; mi++)
#pragma unroll
        for (int ni = 0; ni < 4; ni++)
#pragma unroll
            for (int j = 0; j < 4; j++) acc[mi][ni][j] = 0.f;

    // ---- prologue: A window (348 rows x 128B, SW128), one commit group ----
#pragma unroll
    for (int it = 0; it < 11; it++) {
        int idx = tid + it * 256;                    // need < 348*8 = 2784
        if (idx < AROWS * 8) {
            int row = idx >> 3, qc = idx & 7;
            uint32_t col = (uint32_t)(qc * 16) ^ (uint32_t)((row & 7) * 16);
            cp16(Ab + row * 128 + col, g_inq + (S0 + row) * CIN + qc * 8);
        }
    }
    asm volatile("cp.async.commit_group;\n" ::: "memory");

    // B loader: thread covers (row tid>>1, half tid&1): 4 x 16B, SW128
    const int brow = tid >> 1, bhalf = tid & 1;
    const uint32_t bsw = (uint32_t)((brow & 7) * 16);
    auto issueB = [&](int kk, int s) {
        const __nv_bfloat16* srcB = g_Wq + kk * (NOUT * CIN) + brow * CIN + bhalf * 32;
        uint32_t dstB = smem_u32 + A_BYTES + (uint32_t)s * B_BYTES + (uint32_t)brow * 128;
#pragma unroll
        for (int j = 0; j < 4; j++)
            cp16(dstB + (((uint32_t)(bhalf * 64 + j * 16)) ^ bsw), srcB + j * 8);
        asm volatile("cp.async.commit_group;\n" ::: "memory");
    };

    issueB(0, 0);
    issueB(1, 1);

    // B fragment lane geometry (fixed per warp)
    uint32_t brow_l[2], bswl[2];
#pragma unroll
    for (int np = 0; np < 2; np++) {
        brow_l[np] = wn + np * 16 + (lane >> 4) * 8 + (lane & 7);
        bswl[np]   = (brow_l[np] & 7) * 16;
    }
    const uint32_t bcol_half = ((lane >> 3) & 1) * 16;

#pragma unroll 1
    for (int kk = 0; kk < 9; kk++) {
        if (kk < 8) asm volatile("cp.async.wait_group 1;\n" ::: "memory");
        else        asm volatile("cp.async.wait_group 0;\n" ::: "memory");
        __syncthreads();        // stage kk data visible; stage kk-1 reads done
        if (kk < 7) issueB(kk + 2, (kk + 2) % 3);

        const int kh = kk / 3, kw = kk - kh * 3;
        const int khw = kh * HLW + kw;
        const uint32_t bbase = smem_u32 + A_BYTES + (uint32_t)(kk % 3) * B_BYTES;
        const uint32_t acol0 = (uint32_t)((lane >> 4) * 16);

        uint32_t arow128[4], asw[4];
#pragma unroll
        for (int mi = 0; mi < 4; mi++) {
            int ar = rb[mi] + khw;
            arow128[mi] = Ab + (uint32_t)ar * 128;
            asw[mi]     = (uint32_t)((ar & 7) * 16);
        }

#pragma unroll
        for (int ks = 0; ks < 4; ks++) {
            const uint32_t ac = (uint32_t)(ks * 32) | acol0;   // bits disjoint? ks*32 bits5-6, acol0 bit4 -> OR ok
            uint32_t af[4][4];
#pragma unroll
            for (int mi = 0; mi < 4; mi++)
                ldmatrix_x4(af[mi], arow128[mi] + (ac ^ asw[mi]));

            uint32_t bfr[4][2];
#pragma unroll
            for (int np = 0; np < 2; np++) {
                uint32_t bc = ((uint32_t)(ks * 32) | bcol_half) ^ bswl[np];
                uint32_t r4[4];
                ldmatrix_x4(r4, bbase + brow_l[np] * 128 + bc);
                bfr[np * 2][0] = r4[0]; bfr[np * 2][1] = r4[1];
                bfr[np * 2 + 1][0] = r4[2]; bfr[np * 2 + 1][1] = r4[3];
            }
#pragma unroll
            for (int mi = 0; mi < 4; mi++)
#pragma unroll
                for (int ni = 0; ni < 4; ni++)
                    mma_bf16(acc[mi][ni], af[mi], bfr[ni]);
        }
    }
    __syncthreads();            // all stage-8 A/B reads done before Ep overwrite

    // ---- epilogue: smem transpose, two 64-channel passes ----
    const int m_l  = tid & 127;
    const int half = tid >> 7;
    const int qme  = q0 + m_l;                 // pixel index (may be dummy)
    float* ob = out + (size_t)b * (NOUT * PIX);

#pragma unroll 1
    for (int p = 0; p < 2; p++) {
        if ((wn >> 6) == p) {
#pragma unroll
            for (int mi = 0; mi < 4; mi++)
#pragma unroll
                for (int ni = 0; ni < 4; ni++) {
                    int ncol = (wn & 63) + ni * 8 + 2 * (lane & 3);
                    int mrow = wm + mi * 16 + (lane >> 2);
                    Ep[(ncol + 0) * PADE + mrow]     = acc[mi][ni][0];
                    Ep[(ncol + 1) * PADE + mrow]     = acc[mi][ni][1];
                    Ep[(ncol + 0) * PADE + mrow + 8] = acc[mi][ni][2];
                    Ep[(ncol + 1) * PADE + mrow + 8] = acc[mi][ni][3];
                }
        }
        __syncthreads();
        if (qme < PIX) {
#pragma unroll
            for (int i = 0; i < 32; i++) {
                int n_l = half + 2 * i;        // 0..63
                float v = Ep[n_l * PADE + m_l] + bias_s[p * 64 + n_l];
                stg_cs(ob + (size_t)(p * 64 + n_l) * PIX + qme, v);
            }
        }
        __syncthreads();
    }
}

extern "C" void kernel_launch(void* const* d_in, const int* in_sizes, int n_in,
                              void* d_out, int out_size) {
    const float* inp    = (const float*)d_in[0];
    const float* weight = (const float*)d_in[1];
    const float* bias   = (const float*)d_in[2];
    float* out = (float*)d_out;
    (void)in_sizes; (void)n_in; (void)out_size;

    cudaFuncSetAttribute(qconv_mma, cudaFuncAttributeMaxDynamicSharedMemorySize, SMEM_ALLOC);

    prep_all<<<288 + (32 * HPIX + 255) / 256, 256>>>(weight, inp);
    qconv_mma<<<NCTA, 256, SMEM_ALLOC>>>(bias, out);
}